// round 16
// baseline (speedup 1.0000x reference)
#include <cuda_runtime.h>
#include <cuda_bf16.h>

// Problem constants
#define NB 16
#define NC 256
#define HW 4096
#define ENH_ELEMS (NB * NC * HW)       // 16777216
#define ENT_ELEMS (NB * HW)            // 65536 per map
#define GRID 296                       // 2 blocks/SM x 148 SMs, co-resident
#define NWARPS (GRID * 8)              // 2368
#define PUNITS 8192u                   // pool: one 16KB channel row per unit
#define PMASK  8191u
#define SUNITS 4096u                   // se: 32 px x 256 ch per unit
#define SMASK  4095u
#define OUT_BLOCKS (ENH_ELEMS / 4 / 256)   // 16384
#define ENT_BLOCKS (2 * ENT_ELEMS / 256)   // 512

// ---------------- scratch (device globals; no allocation) ----------------
__device__ float g_pooled[2][NB][NC];
__device__ float g_cw[2][NB][NC];
__device__ float g_se[2][NB][HW];
__device__ float g_psum[2][NB][128];   // per 32-px unit
__device__ float g_psq[2][NB][128];
__device__ float g_thr[2][NB];
__device__ float g_inv[2][NB];
// reset-free counters: each advances by exactly its UNITS per replay
// (works + stop-tokens), UNITS a power of two -> (raw & MASK) = replay index.
__device__ unsigned g_tick_pool, g_tick_se, g_done;
__device__ unsigned g_bar_cnt;          // self-resetting
__device__ volatile unsigned g_bar_gen; // monotonic across launches/replays

// ---------------- entropy: log(p+eps) - (1-p)*log(1-p+eps), p=sigmoid(x) ---
__device__ __forceinline__ float entropy_val(float x) {
    float a = fabsf(x);
    float t = __expf(-a);                  // e^{-|x|}
    float l = __logf(1.0f + t);
    float inv = __fdividef(1.0f, 1.0f + t);
    bool pos = (x >= 0.0f);
    float p      = pos ? inv        : t * inv;   // sigmoid(x)
    float logp   = pos ? -l         : (x - l);   // log p
    float log1mp = pos ? (-x - l)   : -l;        // log (1-p)
    return logp - (1.0f - p) * log1mp;
}

// ---------------- software grid barrier (proven R9-R11) --------------------
__device__ __forceinline__ void grid_bar() {
    __syncthreads();
    if (threadIdx.x == 0) {
        __threadfence();
        unsigned gen = g_bar_gen;              // read BEFORE arrive
        unsigned t = atomicAdd(&g_bar_cnt, 1u);
        if (t == GRID - 1) {
            atomicExch(&g_bar_cnt, 0u);
            __threadfence();
            atomicAdd((unsigned*)&g_bar_gen, 1u);
        } else {
            while (g_bar_gen == gen) __nanosleep(64);
        }
        __threadfence();
    }
    __syncthreads();
}

// ---------------- pool unit: one channel row (ascending addresses) ---------
__device__ __forceinline__ void pool_unit(const float* __restrict__ vis,
                                          const float* __restrict__ text,
                                          int u, int lane) {
    int f  = u >> 12;
    int bc = u & 4095;
    const float4* row = (const float4*)((f ? text : vis) + ((size_t)bc << 12));
    float acc = 0.0f;
    #pragma unroll 8
    for (int k = 0; k < 32; k++) {
        float4 v = row[k * 32 + lane];
        acc += (v.x + v.y) + (v.z + v.w);
    }
    #pragma unroll
    for (int o = 16; o; o >>= 1) acc += __shfl_xor_sync(0xffffffffu, acc, o);
    if (lane == 0) g_pooled[f][bc >> 8][bc & 255] = acc * (1.0f / HW);
}

// ---------------- se unit: 32 coalesced px x 256 ch, descending slabs ------
// Descending so early units read pool's L2-resident tail (same kernel).
// The warp observing the LAST completion also computes thr/inv (stats).
__device__ __forceinline__ void se_unit(const float* __restrict__ vis,
                                        const float* __restrict__ text,
                                        int u, int lane) {
    int slab = 31 - (u >> 7);              // 128 units of 32 px per (f,b)
    int f = slab >> 4, b = slab & 15;
    int ws = u & 127;
    int px = ws * 32 + lane;               // fully coalesced 128B per warp-load
    const float* feat = (f ? text : vis) + ((size_t)(b * NC) << 12) + px;
    const float* cwp  = g_cw[f][b];

    float acc = 0.0f;
    #pragma unroll 8
    for (int c = 0; c < NC; c++) {
        float x = __ldg(feat + ((size_t)c << 12));
        acc = fmaf(entropy_val(x), __ldg(cwp + c), acc);
    }
    g_se[f][b][px] = acc;

    float s = acc, q = acc * acc;
    #pragma unroll
    for (int o = 16; o; o >>= 1) {
        s += __shfl_xor_sync(0xffffffffu, s, o);
        q += __shfl_xor_sync(0xffffffffu, q, o);
    }
    unsigned d = 0;
    if (lane == 0) {
        g_psum[f][b][ws] = s;
        g_psq [f][b][ws] = q;
        __threadfence();                   // publish before arrive
        d = atomicAdd(&g_done, 1u);
    }
    d = __shfl_sync(0xffffffffu, d, 0);
    if ((d & SMASK) == SUNITS - 1) {       // last se unit this replay
        __threadfence();                   // acquire all partials
        int ff = lane >> 4, bb = lane & 15;
        float S = 0.0f, Q = 0.0f;
        #pragma unroll 8
        for (int i = 0; i < 128; i++) { S += g_psum[ff][bb][i]; Q += g_psq[ff][bb][i]; }
        g_thr[ff][bb] = S * (0.5f / HW);   // mean(se)*0.5 (scale-free vs normalize)
        g_inv[ff][bb] = 1.0f / fmaxf(sqrtf(Q), 1e-12f);
    }
}

// ---------------- mlp for one (f,b): blocks 0..31 --------------------------
__device__ __forceinline__ void mlp_block(int bid, int tid, float* sp, float* sh,
                                          const float* __restrict__ w1,
                                          const float* __restrict__ b1,
                                          const float* __restrict__ w2,
                                          const float* __restrict__ b2) {
    int f = bid >> 4, b = bid & 15;
    sp[tid] = g_pooled[f][b][tid];
    __syncthreads();
    if (tid < 64) {
        float acc = b1[tid];
        #pragma unroll 8
        for (int i = 0; i < NC; i++) acc = fmaf(sp[i], w1[i * 64 + tid], acc);
        sh[tid] = fmaxf(acc, 0.0f);
    }
    __syncthreads();
    float acc = b2[tid];
    #pragma unroll 8
    for (int j = 0; j < 64; j++) acc = fmaf(sh[j], w2[j * NC + tid], acc);
    g_cw[f][b][tid] = __fdividef(1.0f, 1.0f + __expf(-acc));
}

// ---------------- fused persistent: pool -> mlp -> se(+stats) --------------
// launch_bounds(256,2): 128-reg budget -> no spills (R10 ran reg-capped at 64).
__global__ void __launch_bounds__(256, 2)
k_fused(const float* __restrict__ vis, const float* __restrict__ text,
        const float* __restrict__ w1, const float* __restrict__ b1,
        const float* __restrict__ w2, const float* __restrict__ b2) {
    __shared__ float sp[NC];
    __shared__ float sh[64];
    int tid = threadIdx.x, bid = blockIdx.x;
    int lane = tid & 31;
    int wg = bid * 8 + (tid >> 5);      // 0..2367

    // ---- phase 1: pool (static first unit + reset-free tickets) ----
    pool_unit(vis, text, wg, lane);
    for (;;) {
        unsigned raw = 0;
        if (lane == 0) raw = atomicAdd(&g_tick_pool, 1u);
        raw = __shfl_sync(0xffffffffu, raw, 0);
        unsigned rel = raw & PMASK;
        if (rel >= PUNITS - NWARPS) break;         // stop token
        pool_unit(vis, text, (int)(NWARPS + rel), lane);
    }
    grid_bar();

    // ---- phase 2: mlp (32 blocks) ----
    if (bid < 32) mlp_block(bid, tid, sp, sh, w1, b1, w2, b2);
    grid_bar();

    // ---- phase 3: se (descending; reads pool's L2-resident data) ----
    se_unit(vis, text, wg, lane);
    for (;;) {
        unsigned raw = 0;
        if (lane == 0) raw = atomicAdd(&g_tick_se, 1u);
        raw = __shfl_sync(0xffffffffu, raw, 0);
        unsigned rel = raw & SMASK;
        if (rel >= SUNITS - NWARPS) break;         // stop token
        se_unit(vis, text, (int)(NWARPS + rel), lane);
    }
    // no epilogue barrier: counters are reset-free (mod power-of-2)
}

// ---------------- K2: blend (ASC, hits se's low-address L2 tail) + ent -----
__global__ void k_out(const float* __restrict__ vis, const float* __restrict__ text,
                      float* __restrict__ out) {
    if (blockIdx.x >= OUT_BLOCKS) {
        int idx = (blockIdx.x - OUT_BLOCKS) * 256 + threadIdx.x;   // 0..131071
        int f   = idx >> 16;
        int rem = idx & 65535;
        int b   = rem >> 12;
        int pix = rem & 4095;
        __stcs(out + ENH_ELEMS + idx, g_se[f][b][pix] * g_inv[f][b]);
        return;
    }
    int idx4 = blockIdx.x * 256 + threadIdx.x;      // 0 .. 4194303
    int pix4 = idx4 & 1023;                         // HW/4 = 1024
    int b    = idx4 >> 18;                          // / (NC*1024)
    float thr_v = g_thr[0][b];
    float thr_t = g_thr[1][b];
    float4 sev = ((const float4*)g_se[0][b])[pix4];
    float4 set = ((const float4*)g_se[1][b])[pix4];
    float4 v = __ldcs(((const float4*)vis) + idx4);   // last use: evict-first
    float4 t = __ldcs(((const float4*)text) + idx4);
    float4 o;
    o.x = (sev.x < thr_v) ? v.x : ((set.x < thr_t) ? t.x : 0.0f);
    o.y = (sev.y < thr_v) ? v.y : ((set.y < thr_t) ? t.y : 0.0f);
    o.z = (sev.z < thr_v) ? v.z : ((set.z < thr_t) ? t.z : 0.0f);
    o.w = (sev.w < thr_v) ? v.w : ((set.w < thr_t) ? t.w : 0.0f);
    __stcs(((float4*)out) + idx4, o);                 // write-once: stream
}

// ---------------- launch ----------------
extern "C" void kernel_launch(void* const* d_in, const int* in_sizes, int n_in,
                              void* d_out, int out_size) {
    const float* vis  = (const float*)d_in[0];
    const float* text = (const float*)d_in[1];
    const float* w1   = (const float*)d_in[2];
    const float* b1   = (const float*)d_in[3];
    const float* w2   = (const float*)d_in[4];
    const float* b2   = (const float*)d_in[5];
    float* out = (float*)d_out;

    k_fused<<<GRID, 256>>>(vis, text, w1, b1, w2, b2);
    k_out  <<<OUT_BLOCKS + ENT_BLOCKS, 256>>>(vis, text, out);
}

// round 17
// speedup vs baseline: 1.1296x; 1.1296x over previous
#include <cuda_runtime.h>
#include <cuda_bf16.h>

// Problem constants
#define NB 16
#define NC 256
#define HW 4096
#define ENH_ELEMS (NB * NC * HW)       // 16777216
#define ENT_ELEMS (NB * HW)            // 65536 per map
#define SE_BLOCKS 512
#define OUT_BLOCKS (ENH_ELEMS / 4 / 256)   // 16384
#define ENT_BLOCKS (2 * ENT_ELEMS / 256)   // 512

// ---------------- scratch (device globals; no allocation) ----------------
__device__ float g_pooled[2][NB][NC];
__device__ float g_cw[2][NB][NC];
__device__ float g_se[2][NB][HW];
__device__ float g_psum[2][NB][16];
__device__ float g_psq[2][NB][16];
__device__ float g_thr[2][NB];
__device__ float g_inv[2][NB];
// reset-free counters: each advances by an exact count per replay; count is a
// power of two, so (value & mask) gives the within-replay index. No resets.
__device__ unsigned g_cnt_pool[2][NB];   // +256 per replay each
__device__ unsigned g_cnt_se;            // +512 per replay

// ---------------- entropy: log(p+eps) - (1-p)*log(1-p+eps), p=sigmoid(x) ---
// softplus form: log p = -softplus(-x), log(1-p) = -softplus(x)
__device__ __forceinline__ float entropy_val(float x) {
    float a = fabsf(x);
    float t = __expf(-a);                  // e^{-|x|}
    float l = __logf(1.0f + t);
    float inv = __fdividef(1.0f, 1.0f + t);
    bool pos = (x >= 0.0f);
    float p      = pos ? inv        : t * inv;   // sigmoid(x)
    float logp   = pos ? -l         : (x - l);   // log p
    float log1mp = pos ? (-x - l)   : -l;        // log (1-p)
    return logp - (1.0f - p) * log1mp;
}

// ---------------- K1: pool (ascending B-MAJOR, f inner) + inline MLP -------
// Block = one (b,c,f) channel row. The block that completes a (f,b)'s 256th
// row runs that (f,b)'s channel-attention MLP inline (removes k_mlp launch).
__global__ void k_pool(const float* __restrict__ vis, const float* __restrict__ text,
                       const float* __restrict__ w1, const float* __restrict__ b1,
                       const float* __restrict__ w2, const float* __restrict__ b2) {
    int id  = blockIdx.x;             // 0..8191, ascending b
    int b   = id >> 9;
    int rem = id & 511;
    int c   = rem >> 1;
    int f   = rem & 1;
    int tid = threadIdx.x;            // 128 threads
    const float4* src = (const float4*)((f ? text : vis) + ((size_t)((b << 8) | c) << 12));
    float acc = 0.0f;
    #pragma unroll
    for (int k = 0; k < 8; k++) {
        float4 v = src[k * 128 + tid];
        acc += (v.x + v.y) + (v.z + v.w);
    }
    #pragma unroll
    for (int o = 16; o; o >>= 1) acc += __shfl_xor_sync(0xffffffffu, acc, o);
    __shared__ float s[4];
    __shared__ bool mlp_turn;
    if ((tid & 31) == 0) s[tid >> 5] = acc;
    __syncthreads();
    if (tid == 0) {
        float tsum = (s[0] + s[1]) + (s[2] + s[3]);
        g_pooled[f][b][c] = tsum * (1.0f / HW);
        __threadfence();                               // publish before arrive
        unsigned d = atomicAdd(&g_cnt_pool[f][b], 1u); // reset-free, +256/replay
        mlp_turn = ((d & 255u) == 255u);
    }
    __syncthreads();
    if (!mlp_turn) return;

    // ---- inline MLP for this (f,b): cw = sigmoid(relu(p@w1+b1)@w2+b2) ----
    __threadfence();                   // acquire all 256 pooled values
    __shared__ float sp[NC];
    __shared__ float sh[64];
    sp[tid]       = g_pooled[f][b][tid];
    sp[tid + 128] = g_pooled[f][b][tid + 128];
    __syncthreads();
    if (tid < 64) {
        float h = b1[tid];
        #pragma unroll 8
        for (int i = 0; i < NC; i++) h = fmaf(sp[i], w1[i * 64 + tid], h);
        sh[tid] = fmaxf(h, 0.0f);
    }
    __syncthreads();
    #pragma unroll
    for (int cc = tid; cc < NC; cc += 128) {
        float o = b2[cc];
        #pragma unroll 8
        for (int j = 0; j < 64; j++) o = fmaf(sh[j], w2[j * NC + cc], o);
        g_cw[f][b][cc] = __fdividef(1.0f, 1.0f + __expf(-o));
    }
}

// ---------------- K2: se (DESCENDING b-major) + last-block stats -----------
// Starts at (b15, text) = k_pool's L2-resident tail; ends at b0 (both feats),
// which is exactly what k_out reads first.
__global__ void k_se(const float* __restrict__ vis, const float* __restrict__ text) {
    int bid   = blockIdx.x;           // 512 blocks
    int pair  = 31 - (bid >> 4);      // descending (b,f), f inner
    int b     = pair >> 1;
    int f     = pair & 1;
    int chunk = bid & 15;             // 16 chunks of 256 pixels per slab
    int pix   = chunk * 256 + threadIdx.x;
    const float* feat = (f ? text : vis) + (((size_t)b << 8) << 12) + pix;

    __shared__ float scw[NC];
    scw[threadIdx.x] = g_cw[f][b][threadIdx.x];
    __syncthreads();

    float acc = 0.0f;
    #pragma unroll 8
    for (int c = 0; c < NC; c++) {
        float x = feat[(size_t)c << 12];
        acc = fmaf(entropy_val(x), scw[c], acc);
    }
    g_se[f][b][pix] = acc;

    float s = acc, q = acc * acc;
    #pragma unroll
    for (int o = 16; o; o >>= 1) {
        s += __shfl_xor_sync(0xffffffffu, s, o);
        q += __shfl_xor_sync(0xffffffffu, q, o);
    }
    __shared__ float ss[8], sq[8];
    __shared__ bool last;
    if ((threadIdx.x & 31) == 0) { ss[threadIdx.x >> 5] = s; sq[threadIdx.x >> 5] = q; }
    __syncthreads();
    if (threadIdx.x == 0) {
        float S = 0.0f, Q = 0.0f;
        #pragma unroll
        for (int i = 0; i < 8; i++) { S += ss[i]; Q += sq[i]; }
        g_psum[f][b][chunk] = S;
        g_psq [f][b][chunk] = Q;
        __threadfence();                               // publish partials
        unsigned t = atomicAdd(&g_cnt_se, 1u);         // reset-free, +512/replay
        last = ((t & 511u) == 511u);
    }
    __syncthreads();
    if (last && threadIdx.x < 32) {                    // final stats
        __threadfence();                               // acquire all partials
        int ff = threadIdx.x >> 4, bb = threadIdx.x & 15;
        float S = 0.0f, Q = 0.0f;
        #pragma unroll
        for (int i = 0; i < 16; i++) { S += g_psum[ff][bb][i]; Q += g_psq[ff][bb][i]; }
        g_thr[ff][bb] = S * (0.5f / HW);               // mean(se)*0.5 (scale-free)
        g_inv[ff][bb] = 1.0f / fmaxf(sqrtf(Q), 1e-12f);
    }
}

// ---------------- K3: blend (ASC b — hits se's b0-b3 tail) + ent tail ------
__global__ void k_out(const float* __restrict__ vis, const float* __restrict__ text,
                      float* __restrict__ out) {
    if (blockIdx.x >= OUT_BLOCKS) {
        // normalized entropy maps
        int idx = (blockIdx.x - OUT_BLOCKS) * 256 + threadIdx.x;   // 0..131071
        int f   = idx >> 16;
        int rem = idx & 65535;
        int b   = rem >> 12;
        int pix = rem & 4095;
        __stcs(out + ENH_ELEMS + idx, g_se[f][b][pix] * g_inv[f][b]);
        return;
    }
    int idx4 = blockIdx.x * 256 + threadIdx.x;      // 0 .. 4194303
    int pix4 = idx4 & 1023;                         // HW/4 = 1024
    int b    = idx4 >> 18;                          // / (NC*1024)
    float thr_v = g_thr[0][b];
    float thr_t = g_thr[1][b];
    float4 sev = ((const float4*)g_se[0][b])[pix4];
    float4 set = ((const float4*)g_se[1][b])[pix4];
    float4 v = __ldcs(((const float4*)vis) + idx4);   // last use: evict-first
    float4 t = __ldcs(((const float4*)text) + idx4);
    float4 o;
    o.x = (sev.x < thr_v) ? v.x : ((set.x < thr_t) ? t.x : 0.0f);
    o.y = (sev.y < thr_v) ? v.y : ((set.y < thr_t) ? t.y : 0.0f);
    o.z = (sev.z < thr_v) ? v.z : ((set.z < thr_t) ? t.z : 0.0f);
    o.w = (sev.w < thr_v) ? v.w : ((set.w < thr_t) ? t.w : 0.0f);
    __stcs(((float4*)out) + idx4, o);                 // write-once: stream
}

// ---------------- launch ----------------
extern "C" void kernel_launch(void* const* d_in, const int* in_sizes, int n_in,
                              void* d_out, int out_size) {
    const float* vis  = (const float*)d_in[0];
    const float* text = (const float*)d_in[1];
    const float* w1   = (const float*)d_in[2];
    const float* b1   = (const float*)d_in[3];
    const float* w2   = (const float*)d_in[4];
    const float* b2   = (const float*)d_in[5];
    float* out = (float*)d_out;

    k_pool<<<2 * NB * NC, 128>>>(vis, text, w1, b1, w2, b2);
    k_se  <<<SE_BLOCKS, 256>>>(vis, text);
    k_out <<<OUT_BLOCKS + ENT_BLOCKS, 256>>>(vis, text, out);
}